// round 15
// baseline (speedup 1.0000x reference)
#include <cuda_runtime.h>
#include <cuda_bf16.h>
#include <math.h>
#include <stdint.h>

// ---------------------------------------------------------------------------
// ChildSumTreeLSTM via HMMA (mma.sync bf16), fp32 accuracy via 3-term split:
//   acc = Ah*Bh + Al*Bh + Ah*Bl   (packed [hi|lo] K=512 rows, 3 passes/chunk)
// R12 structure (best: 882.1us) + fused FFMA path for tiny levels l=3..0
// (one kernel per level instead of GEMM+combine pairs).
// ---------------------------------------------------------------------------

#define N_NODES   87381
#define N_INT     21845
#define LEAF_OFF  21845
#define N_LEAVES  65536
#define KP        512          // packed row: [hi(256) | lo(256)]
#define NK0       8            // 256/32 k0 chunks

#define LSTG      35840        // Ah 10240 | Al 10240 | Bh 7680 | Bl 7680
#define LPITCH    100
#define LEAF_SMEM (2 * LSTG)   // 71680 >= 128*LPITCH*4 (51200)

#define GSTG      40960        // Ah 10240 | Al 10240 | Bh 10240 | Bl 10240
#define SPITCH    132
#define BIG_SMEM  (2 * GSTG)   // 81920 >= SPITCH*128*4 (67584)

// --------------------------- device scratch --------------------------------
__device__ __align__(256) float         g_XW[(size_t)N_INT * 1024];     // 4j+g
__device__ __align__(256) float         g_c [(size_t)N_NODES * 256];
__device__ __align__(256) __nv_bfloat16 g_h [(size_t)N_NODES * KP];
__device__ __align__(256) __nv_bfloat16 g_x [(size_t)N_NODES * KP];
__device__ __align__(256) __nv_bfloat16 g_hs[(size_t)16384 * KP];
__device__ __align__(256) float         g_iouh[(size_t)16384 * 768];    // 3j+g
__device__ __align__(256) float         g_fh  [(size_t)65536 * 256];
__device__ __align__(256) __nv_bfloat16 g_Wcat [1024 * KP];             // 4j+g
__device__ __align__(256) __nv_bfloat16 g_Wiou [ 768 * KP];             // 3j+g
__device__ __align__(256) __nv_bfloat16 g_Wiouh[ 768 * KP];             // 3j+g
__device__ __align__(256) __nv_bfloat16 g_Wfh  [ 256 * KP];
__device__ float g_bcat[1024];                                          // 4j+g
__device__ float g_b3[768];                                             // 3j+g

// --------------------------- helpers ---------------------------------------
__device__ __forceinline__ float fsig(float v) {
    return __fdividef(1.0f, 1.0f + __expf(-v));
}
__device__ __forceinline__ float ftanh(float v) {
    float a = fabsf(v);
    float e = __expf(-2.0f * a);
    float t = __fdividef(1.0f - e, 1.0f + e);
    return copysignf(t, v);
}
// packed [hi|lo] write
__device__ __forceinline__ void write2(__nv_bfloat16* row, int j, float v) {
    __nv_bfloat16 hi = __float2bfloat16(v);
    __nv_bfloat16 lo = __float2bfloat16(v - __bfloat162float(hi));
    row[j] = hi; row[256 + j] = lo;
}
__device__ __forceinline__ float rec2(const __nv_bfloat16* row, int j) {
    return __bfloat162float(row[j]) + __bfloat162float(row[256 + j]);
}
__device__ __forceinline__ uint32_t smem_u32(const void* p) {
    uint32_t a;
    asm("{ .reg .u64 t; cvta.to.shared.u64 t, %1; cvt.u32.u64 %0, t; }" : "=r"(a) : "l"(p));
    return a;
}
__device__ __forceinline__ void cp_async16(uint32_t dst, const void* src, int sz) {
    asm volatile("cp.async.ca.shared.global [%0], [%1], 16, %2;"
                 :: "r"(dst), "l"(src), "r"(sz) : "memory");
}
__device__ __forceinline__ void ldmatrix_x4(uint32_t* r, uint32_t addr) {
    asm volatile("ldmatrix.sync.aligned.m8n8.x4.shared.b16 {%0,%1,%2,%3}, [%4];"
                 : "=r"(r[0]), "=r"(r[1]), "=r"(r[2]), "=r"(r[3]) : "r"(addr));
}
__device__ __forceinline__ void mma16816(float* c, const uint32_t* a, const uint32_t* b) {
    asm volatile(
        "mma.sync.aligned.m16n8k16.row.col.f32.bf16.bf16.f32 "
        "{%0,%1,%2,%3}, {%4,%5,%6,%7}, {%8,%9}, {%0,%1,%2,%3};"
        : "+f"(c[0]), "+f"(c[1]), "+f"(c[2]), "+f"(c[3])
        : "r"(a[0]), "r"(a[1]), "r"(a[2]), "r"(a[3]), "r"(b[0]), "r"(b[1]));
}

// --------------------------- pack kernels ----------------------------------
__global__ void split_x(const float* __restrict__ x) {
    const size_t node = blockIdx.x;
    const int j = threadIdx.x;
    write2(&g_x[node * KP], j, x[node * 256 + j]);
}

// Wcat rows p = 4j+g (internal x-GEMM)
__global__ void pack_wcat(const float* __restrict__ Wix, const float* __restrict__ bix,
                          const float* __restrict__ bih,
                          const float* __restrict__ Wfx, const float* __restrict__ bfx,
                          const float* __restrict__ bfh) {
    const int p = blockIdx.x;           // 0..1023
    const int jj = threadIdx.x;
    const int j = p >> 2, g = p & 3;
    float v = (g < 3) ? Wix[(g * 256 + j) * 256 + jj] : Wfx[j * 256 + jj];
    write2(&g_Wcat[(size_t)p * KP], jj, v);
    if (jj == 0)
        g_bcat[p] = (g < 3) ? (bix[g * 256 + j] + bih[g * 256 + j]) : (bfx[j] + bfh[j]);
}

// Merged: Wiou (leaf GEMM, 3j+g), Wiouh (3j+g), Wfh
__global__ void pack_rest(const float* __restrict__ Wix, const float* __restrict__ bix,
                          const float* __restrict__ bih,
                          const float* __restrict__ Wiouh, const float* __restrict__ Wfh) {
    const int b = blockIdx.x;           // 0..1791
    const int jj = threadIdx.x;
    if (b < 768) {                      // Wiou row p = 3j+g
        const int j = b / 3, g = b % 3;
        write2(&g_Wiou[(size_t)b * KP], jj, Wix[(g * 256 + j) * 256 + jj]);
        if (jj == 0) g_b3[b] = bix[g * 256 + j] + bih[g * 256 + j];
    } else if (b < 1536) {              // Wiouh row p = 3j+g
        const int p = b - 768;
        const int j = p / 3, g = p % 3;
        write2(&g_Wiouh[(size_t)p * KP], jj, Wiouh[(g * 256 + j) * 256 + jj]);
    } else {                            // Wfh row r
        const int r = b - 1536;
        write2(&g_Wfh[(size_t)r * KP], jj, Wfh[r * 256 + jj]);
    }
}

// --------------------------- leaf GEMM (128x96, 2-stage, occ2) -------------
// Per k0: load Ah/Al/Bh/Bl tiles once; 3 compute passes (AhBh, AlBh, AhBl).
// Fused activation + level-7 hsum (in-place smem staging).
__global__ __launch_bounds__(256, 2)
void gemm_leaf(const __nv_bfloat16* __restrict__ A,      // g_x + LEAF_OFF*KP
               const __nv_bfloat16* __restrict__ B) {    // g_Wiou
    extern __shared__ __align__(16) char smd[];
    const int tid  = threadIdx.x;
    const int wid  = tid >> 5;
    const int lane = tid & 31;
    const int bm = blockIdx.y * 128;
    const int bn = blockIdx.x * 96;
    const int wm = (wid >> 1) * 32;
    const int wn = (wid & 1) * 48;
    const uint32_t sb = smem_u32(smd);

    float acc[2][6][4];
#pragma unroll
    for (int i = 0; i < 2; i++)
#pragma unroll
        for (int n = 0; n < 6; n++)
#pragma unroll
            for (int q = 0; q < 4; q++) acc[i][n][q] = 0.0f;

    // 1792 cp.async slots: Ah 512 | Al 512 | Bh 384 | Bl 384
#define LLOAD(c, st) do {                                                        \
        const int k0e = (c) * 32;                                                \
        uint32_t bs = sb + (st) * LSTG;                                          \
        _Pragma("unroll")                                                        \
        for (int s = 0; s < 7; s++) {                                            \
            int id = tid + s * 256;                                              \
            if (id < 512) {                                                      \
                int r = id >> 2, q = id & 3;                                     \
                cp_async16(bs + r * 80 + q * 16,                                 \
                           A + (size_t)(bm + r) * KP + k0e + q * 8, 16);         \
            } else if (id < 1024) {                                              \
                int o = id - 512; int r = o >> 2, q = o & 3;                     \
                cp_async16(bs + 10240 + r * 80 + q * 16,                         \
                           A + (size_t)(bm + r) * KP + 256 + k0e + q * 8, 16);   \
            } else if (id < 1408) {                                              \
                int o = id - 1024; int r = o >> 2, q = o & 3;                    \
                cp_async16(bs + 20480 + r * 80 + q * 16,                         \
                           B + (size_t)(bn + r) * KP + k0e + q * 8, 16);         \
            } else {                                                             \
                int o = id - 1408; int r = o >> 2, q = o & 3;                    \
                cp_async16(bs + 28160 + r * 80 + q * 16,                         \
                           B + (size_t)(bn + r) * KP + 256 + k0e + q * 8, 16);   \
            }                                                                    \
        }                                                                        \
        asm volatile("cp.async.commit_group;" ::: "memory");                     \
    } while (0)

    LLOAD(0, 0);
    const uint32_t lrow = lane & 15;
    const uint32_t lcol = (lane >> 4) * 16;

    for (int k0 = 0; k0 < NK0; k0++) {
        const int st = k0 & 1;
        if (k0 + 1 < NK0) {
            LLOAD(k0 + 1, st ^ 1);
            asm volatile("cp.async.wait_group 1;" ::: "memory");
        } else {
            asm volatile("cp.async.wait_group 0;" ::: "memory");
        }
        __syncthreads();

#pragma unroll 1
        for (int pass = 0; pass < 3; pass++) {
            const uint32_t aoff = (pass == 1) ? 10240u : 0u;
            const uint32_t boff = 20480u + ((pass == 2) ? 7680u : 0u);
            const uint32_t abase = sb + st * LSTG + aoff + (wm + lrow) * 80 + lcol;
            const uint32_t bbase = sb + st * LSTG + boff + (wn + lrow) * 80 + lcol;
#pragma unroll
            for (int ks = 0; ks < 2; ks++) {
                const uint32_t ko = ks * 32;
                uint32_t a[2][4];
                ldmatrix_x4(a[0], abase + ko);
                ldmatrix_x4(a[1], abase + 16 * 80 + ko);
                uint32_t bf[6][2];
#pragma unroll
                for (int j = 0; j < 3; j++) {
                    uint32_t r[4];
                    ldmatrix_x4(r, bbase + j * 16 * 80 + ko);
                    bf[2 * j][0] = r[0]; bf[2 * j][1] = r[2];
                    bf[2 * j + 1][0] = r[1]; bf[2 * j + 1][1] = r[3];
                }
#pragma unroll
                for (int i = 0; i < 2; i++)
#pragma unroll
                    for (int n = 0; n < 6; n++)
                        mma16816(acc[i][n], a[i], bf[n]);
            }
        }
        __syncthreads();
    }
#undef LLOAD

    // ---- stage tile to smem (aliases pipeline buffers) ----
    float* Cs = (float*)smd;
#pragma unroll
    for (int i = 0; i < 2; i++) {
        const int r = wm + i * 16 + (lane >> 2);
#pragma unroll
        for (int n = 0; n < 6; n++) {
            const int col = wn + n * 8 + (lane & 3) * 2;
            *(float2*)(Cs + r * LPITCH + col) = make_float2(acc[i][n][0], acc[i][n][1]);
            *(float2*)(Cs + (r + 8) * LPITCH + col) = make_float2(acc[i][n][2], acc[i][n][3]);
        }
    }
    __syncthreads();

    // ---- leaf activation: 128 rows x 32 features, 2 features per thread ----
    const int j0 = 32 * blockIdx.x;
#pragma unroll 2
    for (int it = 0; it < 8; it++) {
        const int idx = it * 256 + tid;
        const int r = idx >> 4;
        const int t = 2 * (idx & 15);
        float* cr = Cs + r * LPITCH + 3 * t;
        const float* bb = g_b3 + bn + 3 * t;
        float i0 = fsig (cr[0] + bb[0]);
        float o0 = fsig (cr[1] + bb[1]);
        float u0 = ftanh(cr[2] + bb[2]);
        float c0 = i0 * u0;
        float h0 = o0 * ftanh(c0);
        float i1 = fsig (cr[3] + bb[3]);
        float o1 = fsig (cr[4] + bb[4]);
        float u1 = ftanh(cr[5] + bb[5]);
        float c1 = i1 * u1;
        float h1 = o1 * ftanh(c1);

        const size_t node = (size_t)LEAF_OFF + bm + r;
        const int j = j0 + t;
        *(float2*)(g_c + node * 256 + j) = make_float2(c0, c1);

        __nv_bfloat16 hh0 = __float2bfloat16(h0);
        __nv_bfloat16 hh1 = __float2bfloat16(h1);
        float l0 = h0 - __bfloat162float(hh0);
        float l1 = h1 - __bfloat162float(hh1);
        uint32_t hiw; { __nv_bfloat162 p2 = {hh0, hh1}; hiw = *reinterpret_cast<uint32_t*>(&p2); }
        uint32_t low; { __nv_bfloat162 p2 = __floats2bfloat162_rn(l0, l1);
                        low = *reinterpret_cast<uint32_t*>(&p2); }
        uint32_t* hrow = (uint32_t*)(g_h + node * KP + j);
        hrow[0] = hiw;
        hrow[128] = low;

        // in-place fp32 h staging for the fused hsum pass
        cr[0] = h0;
        cr[3] = h1;
    }
    __syncthreads();

    // ---- fused level-7 hsum: 32 parents x 32 features per CTA ----
    const int kb = 32 * blockIdx.y;
#pragma unroll
    for (int v = 0; v < 4; v++) {
        const int lin = v * 256 + tid;
        const int pp = lin >> 5;
        const int tt = lin & 31;
        const float* hb = Cs + (4 * pp) * LPITCH + 3 * tt;
        float s = hb[0] + hb[LPITCH] + hb[2 * LPITCH] + hb[3 * LPITCH];
        write2(&g_hs[(size_t)(kb + pp) * KP], j0 + tt, s);
    }
}

// --------------------------- generic 128x128 mainloop ----------------------
__device__ __forceinline__ void mainloop128(
    const __nv_bfloat16* __restrict__ A, const __nv_bfloat16* __restrict__ B,
    int M, int bm, int bn, uint32_t sb, int tid, int wid, int lane,
    float (&acc)[2][8][4])
{
    const int wm = (wid >> 1) * 32;
    const int wn = (wid & 1) * 64;

    // 2048 cp.async slots: Ah 512 | Al 512 | Bh 512 | Bl 512
#define GLOAD(c, st) do {                                                        \
        const int k0e = (c) * 32;                                                \
        uint32_t bs = sb + (st) * GSTG;                                          \
        _Pragma("unroll")                                                        \
        for (int s = 0; s < 8; s++) {                                            \
            int id = tid + s * 256;                                              \
            int seg = id >> 9;                                                   \
            int o = id & 511;                                                    \
            int r = o >> 2, q = o & 3;                                           \
            if (seg == 0)                                                        \
                cp_async16(bs + r * 80 + q * 16,                                 \
                           A + (size_t)(bm + r) * KP + k0e + q * 8,              \
                           (bm + r < M) ? 16 : 0);                               \
            else if (seg == 1)                                                   \
                cp_async16(bs + 10240 + r * 80 + q * 16,                         \
                           A + (size_t)(bm + r) * KP + 256 + k0e + q * 8,        \
                           (bm + r < M) ? 16 : 0);                               \
            else if (seg == 2)                                                   \
                cp_async16(bs + 20480 + r * 80 + q * 16,                         \
                           B + (size_t)(bn + r) * KP + k0e + q * 8, 16);         \
            else                                                                 \
                cp_async16(bs + 30720 + r * 80 + q * 16,                         \
                           B + (size_t)(bn + r) * KP + 256 + k0e + q * 8, 16);   \
        }                                                                        \
        asm volatile("cp.async.commit_group;" ::: "memory");                     \
    } while (0)

    GLOAD(0, 0);
    const uint32_t lrow = lane & 15;
    const uint32_t lcol = (lane >> 4) * 16;

    for (int k0 = 0; k0 < NK0; k0++) {
        const int st = k0 & 1;
        if (k0 + 1 < NK0) {
            GLOAD(k0 + 1, st ^ 1);
            asm volatile("cp.async.wait_group 1;" ::: "memory");
        } else {
            asm volatile("cp.async.wait_group 0;" ::: "memory");
        }
        __syncthreads();

#pragma unroll 1
        for (int pass = 0; pass < 3; pass++) {
            const uint32_t aoff = (pass == 1) ? 10240u : 0u;
            const uint32_t boff = 20480u + ((pass == 2) ? 10240u : 0u);
            const uint32_t abase = sb + st * GSTG + aoff + (wm + lrow) * 80 + lcol;
            const uint32_t bbase = sb + st * GSTG + boff + (wn + lrow) * 80 + lcol;
#pragma unroll
            for (int ks = 0; ks < 2; ks++) {
                const uint32_t ko = ks * 32;
                uint32_t a[2][4];
                ldmatrix_x4(a[0], abase + ko);
                ldmatrix_x4(a[1], abase + 16 * 80 + ko);
                uint32_t bf[8][2];
#pragma unroll
                for (int j = 0; j < 4; j++) {
                    uint32_t r[4];
                    ldmatrix_x4(r, bbase + j * 16 * 80 + ko);
                    bf[2 * j][0] = r[0]; bf[2 * j][1] = r[2];
                    bf[2 * j + 1][0] = r[1]; bf[2 * j + 1][1] = r[3];
                }
#pragma unroll
                for (int i = 0; i < 2; i++)
#pragma unroll
                    for (int n = 0; n < 8; n++)
                        mma16816(acc[i][n], a[i], bf[n]);
            }
        }
        __syncthreads();
    }
#undef GLOAD
}

// --------------------------- dual-problem GEMM -----------------------------
__global__ __launch_bounds__(256, 2)
void gemm_dual(const __nv_bfloat16* A1, const __nv_bfloat16* B1, float* C1, int M1, int N1,
               const __nv_bfloat16* A2, const __nv_bfloat16* B2, float* C2, int M2, int N2) {
    extern __shared__ __align__(16) char smd[];
    const int tid  = threadIdx.x;
    const int wid  = tid >> 5;
    const int lane = tid & 31;
    const uint32_t sb = smem_u32(smd);

    const __nv_bfloat16 *A, *B;
    float* C;
    int M, Ntot, bm, bn;
    {
        const int nt1 = N1 >> 7, mt1 = (M1 + 127) >> 7;
        const int t1 = nt1 * mt1;
        int idx = blockIdx.x;
        if (idx < t1) {
            A = A1; B = B1; C = C1; M = M1; Ntot = N1;
            bm = (idx / nt1) * 128; bn = (idx % nt1) * 128;
        } else {
            idx -= t1;
            const int nt2 = N2 >> 7;
            A = A2; B = B2; C = C2; M = M2; Ntot = N2;
            bm = (idx / nt2) * 128; bn = (idx % nt2) * 128;
        }
    }

    float acc[2][8][4];
#pragma unroll
    for (int i = 0; i < 2; i++)
#pragma unroll
        for (int n = 0; n < 8; n++)
#pragma unroll
            for (int q = 0; q < 4; q++) acc[i][n][q] = 0.0f;

    mainloop128(A, B, M, bm, bn, sb, tid, wid, lane, acc);

    const int wm = (wid >> 1) * 32;
    const int wn = (wid & 1) * 64;
#pragma unroll
    for (int i = 0; i < 2; i++) {
        const int ra = bm + wm + i * 16 + (lane >> 2);
        const int rb = ra + 8;
#pragma unroll
        for (int n = 0; n < 8; n++) {
            const int col = bn + wn + n * 8 + (lane & 3) * 2;
            if (ra < M)
                *(float2*)(C + (size_t)ra * Ntot + col) =
                    make_float2(acc[i][n][0], acc[i][n][1]);
            if (rb < M)
                *(float2*)(C + (size_t)rb * Ntot + col) =
                    make_float2(acc[i][n][2], acc[i][n][3]);
        }
    }
}

// --------------------------- internal x-GEMM -------------------------------
__global__ __launch_bounds__(256, 2)
void gemm_big(const __nv_bfloat16* __restrict__ A, const __nv_bfloat16* __restrict__ B) {
    extern __shared__ __align__(16) char smd[];
    const int tid  = threadIdx.x;
    const int wid  = tid >> 5;
    const int lane = tid & 31;
    const int bm = blockIdx.y * 128;
    const int bn = blockIdx.x * 128;
    const int M = N_INT;
    const uint32_t sb = smem_u32(smd);

    float acc[2][8][4];
#pragma unroll
    for (int i = 0; i < 2; i++)
#pragma unroll
        for (int n = 0; n < 8; n++)
#pragma unroll
            for (int q = 0; q < 4; q++) acc[i][n][q] = 0.0f;

    mainloop128(A, B, M, bm, bn, sb, tid, wid, lane, acc);

    // stage C tile, then coalesced float4 XW stores (+bias)
    float* Cs = (float*)smd;
    const int wm = (wid >> 1) * 32;
    const int wn = (wid & 1) * 64;
#pragma unroll
    for (int i = 0; i < 2; i++) {
        const int ral = wm + i * 16 + (lane >> 2);
#pragma unroll
        for (int n = 0; n < 8; n++) {
            const int col = wn + n * 8 + (lane & 3) * 2;
            *(float2*)(Cs + ral * SPITCH + col) = make_float2(acc[i][n][0], acc[i][n][1]);
            *(float2*)(Cs + (ral + 8) * SPITCH + col) = make_float2(acc[i][n][2], acc[i][n][3]);
        }
    }
    __syncthreads();

#pragma unroll 4
    for (int it = 0; it < 16; it++) {
        const int idx = it * 256 + tid;
        const int r = idx >> 5;
        const int t = idx & 31;
        const int row = bm + r;
        if (row >= M) continue;
        float4 v = *(float4*)(Cs + r * SPITCH + 4 * t);
        const float4 b = *(const float4*)(g_bcat + bn + 4 * t);
        v.x += b.x; v.y += b.y; v.z += b.z; v.w += b.w;
        *(float4*)(g_XW + (size_t)row * 1024 + bn + 4 * t) = v;
    }
}

// --------------------------- fused combine + parent hsum -------------------
__global__ void combine_fused(int node_off, int child_off) {
    __shared__ float hsm[4][256];
    const int s = threadIdx.x >> 8;
    const int j = threadIdx.x & 255;
    const int k = 4 * blockIdx.x + s;
    const size_t node = (size_t)node_off + k;

    const float4 xw = *(const float4*)(g_XW + node * 1024 + 4 * j);
    const float* iouh = &g_iouh[(size_t)k * 768 + 3 * j];

    float iv = fsig (xw.x + iouh[0]);
    float ov = fsig (xw.y + iouh[1]);
    float uv = ftanh(xw.z + iouh[2]);
    const float fx = xw.w;

    float acc = 0.0f;
#pragma unroll
    for (int b = 0; b < 4; b++) {
        size_t ch = (size_t)child_off + 4 * (size_t)k + b;
        float f = fsig(fx + g_fh[(4 * (size_t)k + b) * 256 + j]);
        acc = fmaf(f, g_c[ch * 256 + j], acc);
    }
    float c = fmaf(iv, uv, acc);
    float h = ov * ftanh(c);
    g_c[node * 256 + j] = c;
    write2(&g_h[node * KP], j, h);

    hsm[s][j] = h;
    __syncthreads();
    if (s == 0) {
        float sum = hsm[0][j] + hsm[1][j] + hsm[2][j] + hsm[3][j];
        write2(&g_hs[(size_t)blockIdx.x * KP], j, sum);
    }
}

// --------------------------- fused tiny-level kernel (l<=3) ----------------
// Block = 4 siblings x 256 features (root: 256 threads, s=0 only).
// Computes IOUH and FH dots directly in fp32 from packed bf16 buffers.
// hsum slots are level-disjoint: in at g_hs[hs_in + k], out g_hs[hs_out + blk].
__global__ void level_small(int node_off, int child_off, int hs_in, int hs_out,
                            int has_parent) {
    __shared__ float shs[4][256];
    __shared__ float shch[4][4][256];
    __shared__ float shh[4][256];
    const int s = threadIdx.x >> 8;
    const int j = threadIdx.x & 255;
    const int k = 4 * blockIdx.x + s;
    const size_t node = (size_t)node_off + k;

    shs[s][j] = rec2(&g_hs[(size_t)(hs_in + k) * KP], j);
#pragma unroll
    for (int b = 0; b < 4; b++) {
        size_t ch = (size_t)child_off + 4 * (size_t)k + b;
        shch[s][b][j] = rec2(&g_h[ch * KP], j);
    }
    __syncthreads();

    // iou dots over hsum (rows 3j+g of g_Wiouh)
    const __nv_bfloat16* w0 = g_Wiouh + (size_t)(3 * j + 0) * KP;
    const __nv_bfloat16* w1 = g_Wiouh + (size_t)(3 * j + 1) * KP;
    const __nv_bfloat16* w2 = g_Wiouh + (size_t)(3 * j + 2) * KP;
    float d0 = 0.f, d1 = 0.f, d2 = 0.f;
    for (int kk = 0; kk < 256; kk++) {
        float hv = shs[s][kk];
        d0 = fmaf(hv, rec2(w0, kk), d0);
        d1 = fmaf(hv, rec2(w1, kk), d1);
        d2 = fmaf(hv, rec2(w2, kk), d2);
    }
    // f dots per child (row j of g_Wfh)
    const __nv_bfloat16* wf = g_Wfh + (size_t)j * KP;
    float df[4] = {0.f, 0.f, 0.f, 0.f};
    for (int kk = 0; kk < 256; kk++) {
        float wv = rec2(wf, kk);
        df[0] = fmaf(shch[s][0][kk], wv, df[0]);
        df[1] = fmaf(shch[s][1][kk], wv, df[1]);
        df[2] = fmaf(shch[s][2][kk], wv, df[2]);
        df[3] = fmaf(shch[s][3][kk], wv, df[3]);
    }

    const float4 xw = *(const float4*)(g_XW + node * 1024 + 4 * j);
    float iv = fsig (xw.x + d0);
    float ov = fsig (xw.y + d1);
    float uv = ftanh(xw.z + d2);
    const float fx = xw.w;
    float acc = 0.f;
#pragma unroll
    for (int b = 0; b < 4; b++) {
        size_t ch = (size_t)child_off + 4 * (size_t)k + b;
        acc = fmaf(fsig(fx + df[b]), g_c[ch * 256 + j], acc);
    }
    float c = fmaf(iv, uv, acc);
    float h = ov * ftanh(c);
    g_c[node * 256 + j] = c;
    write2(&g_h[node * KP], j, h);

    shh[s][j] = h;
    __syncthreads();
    if (has_parent && s == 0) {
        float sum = shh[0][j] + shh[1][j] + shh[2][j] + shh[3][j];
        write2(&g_hs[(size_t)(hs_out + blockIdx.x) * KP], j, sum);
    }
}

__global__ void write_out(float* __restrict__ out) {
    int j = threadIdx.x;
    if (blockIdx.x == 0) out[j] = g_c[j];
    else out[256 + j] = __bfloat162float(g_h[j]) + __bfloat162float(g_h[256 + j]);
}

// --------------------------- launcher --------------------------------------
extern "C" void kernel_launch(void* const* d_in, const int* in_sizes, int n_in,
                              void* d_out, int out_size) {
    const float* x      = (const float*)d_in[0];
    const float* W_ioux = (const float*)d_in[1];
    const float* b_ioux = (const float*)d_in[2];
    const float* W_iouh = (const float*)d_in[3];
    const float* b_iouh = (const float*)d_in[4];
    const float* W_fx   = (const float*)d_in[5];
    const float* b_fx   = (const float*)d_in[6];
    const float* W_fh   = (const float*)d_in[7];
    const float* b_fh   = (const float*)d_in[8];

    cudaFuncSetAttribute(gemm_big,  cudaFuncAttributeMaxDynamicSharedMemorySize, BIG_SMEM);
    cudaFuncSetAttribute(gemm_dual, cudaFuncAttributeMaxDynamicSharedMemorySize, BIG_SMEM);
    cudaFuncSetAttribute(gemm_leaf, cudaFuncAttributeMaxDynamicSharedMemorySize, LEAF_SMEM);

    __nv_bfloat16 *xp, *hp, *hsp, *wcp, *wlp, *wip, *wfp;
    float *iouh, *fh;
    cudaGetSymbolAddress((void**)&xp,   g_x);
    cudaGetSymbolAddress((void**)&hp,   g_h);
    cudaGetSymbolAddress((void**)&hsp,  g_hs);
    cudaGetSymbolAddress((void**)&wcp,  g_Wcat);
    cudaGetSymbolAddress((void**)&wlp,  g_Wiou);
    cudaGetSymbolAddress((void**)&wip,  g_Wiouh);
    cudaGetSymbolAddress((void**)&wfp,  g_Wfh);
    cudaGetSymbolAddress((void**)&iouh, g_iouh);
    cudaGetSymbolAddress((void**)&fh,   g_fh);

    // 1-3: pack / split
    split_x<<<N_NODES, 256>>>(x);
    pack_wcat<<<1024, 256>>>(W_ioux, b_ioux, b_iouh, W_fx, b_fx, b_fh);
    pack_rest<<<1792, 256>>>(W_ioux, b_ioux, b_iouh, W_iouh, W_fh);

    // 4: leaf GEMM + fused activation + fused level-7 hsum (PROFILED LAUNCH)
    {
        dim3 grid(8, N_LEAVES / 128);
        gemm_leaf<<<grid, 256, LEAF_SMEM>>>(&xp[(size_t)LEAF_OFF * KP], wlp);
    }

    // 5: internal x-GEMM -> XW
    {
        dim3 grid(8, (N_INT + 127) / 128);
        gemm_big<<<grid, 256, BIG_SMEM>>>(xp, wcp);
    }

    // internal levels l = 7..4: tensor-core dual GEMM + combine
    for (int l = 7; l >= 4; l--) {
        int n = 1 << (2 * l);
        int off = ((1 << (2 * l)) - 1) / 3;
        int choff = off + n;

        {   // fused dual GEMM: IOUH (n x 768) + FH (4n x 256)
            int mt1 = (n + 127) / 128;
            int mt2 = (4 * n + 127) / 128;
            int tiles = mt1 * 6 + mt2 * 2;
            gemm_dual<<<tiles, 256, BIG_SMEM>>>(hsp, wip, iouh, n, 768,
                                                &hp[(size_t)choff * KP], wfp,
                                                fh, 4 * n, 256);
        }
        combine_fused<<<n / 4, 1024>>>(off, choff);
    }

    // tiny levels l = 3..0: fused fp32 kernels (hsum slots: 0 / 64 / 80 / 84)
    level_small<<<16, 1024>>>(21, 85, /*hs_in=*/0,  /*hs_out=*/64, 1);  // l=3
    level_small<<< 4, 1024>>>( 5, 21, /*hs_in=*/64, /*hs_out=*/80, 1);  // l=2
    level_small<<< 1, 1024>>>( 1,  5, /*hs_in=*/80, /*hs_out=*/84, 1);  // l=1
    level_small<<< 1,  256>>>( 0,  1, /*hs_in=*/84, /*hs_out=*/0,  0);  // l=0 (root)

    write_out<<<2, 256>>>((float*)d_out);
}

// round 16
// speedup vs baseline: 1.9279x; 1.9279x over previous
#include <cuda_runtime.h>
#include <cuda_bf16.h>
#include <math.h>
#include <stdint.h>

// ---------------------------------------------------------------------------
// ChildSumTreeLSTM via HMMA (mma.sync bf16), fp32 accuracy via 3-term split:
//   acc = Ah*Bh + Al*Bh + Ah*Bl   (packed [hi|lo] K=512 rows, 3 passes/chunk)
// R12 structure (best: 882.1us) + vectorized split_x + merged pack kernel.
// ---------------------------------------------------------------------------

#define N_NODES   87381
#define N_INT     21845
#define LEAF_OFF  21845
#define N_LEAVES  65536
#define KP        512          // packed row: [hi(256) | lo(256)]
#define NK0       8            // 256/32 k0 chunks

#define LSTG      35840        // Ah 10240 | Al 10240 | Bh 7680 | Bl 7680
#define LPITCH    100
#define LEAF_SMEM (2 * LSTG)   // 71680 >= 128*LPITCH*4 (51200)

#define GSTG      40960        // Ah 10240 | Al 10240 | Bh 10240 | Bl 10240
#define SPITCH    132
#define BIG_SMEM  (2 * GSTG)   // 81920 >= SPITCH*128*4 (67584)

// --------------------------- device scratch --------------------------------
__device__ __align__(256) float         g_XW[(size_t)N_INT * 1024];     // 4j+g
__device__ __align__(256) float         g_c [(size_t)N_NODES * 256];
__device__ __align__(256) __nv_bfloat16 g_h [(size_t)N_NODES * KP];
__device__ __align__(256) __nv_bfloat16 g_x [(size_t)N_NODES * KP];
__device__ __align__(256) __nv_bfloat16 g_hs[(size_t)16384 * KP];
__device__ __align__(256) float         g_iouh[(size_t)16384 * 768];    // 3j+g
__device__ __align__(256) float         g_fh  [(size_t)65536 * 256];
__device__ __align__(256) __nv_bfloat16 g_Wcat [1024 * KP];             // 4j+g
__device__ __align__(256) __nv_bfloat16 g_Wiou [ 768 * KP];             // 3j+g
__device__ __align__(256) __nv_bfloat16 g_Wiouh[ 768 * KP];             // 3j+g
__device__ __align__(256) __nv_bfloat16 g_Wfh  [ 256 * KP];
__device__ float g_bcat[1024];                                          // 4j+g
__device__ float g_b3[768];                                             // 3j+g

// --------------------------- helpers ---------------------------------------
__device__ __forceinline__ float fsig(float v) {
    return __fdividef(1.0f, 1.0f + __expf(-v));
}
__device__ __forceinline__ float ftanh(float v) {
    float a = fabsf(v);
    float e = __expf(-2.0f * a);
    float t = __fdividef(1.0f - e, 1.0f + e);
    return copysignf(t, v);
}
// packed [hi|lo] write
__device__ __forceinline__ void write2(__nv_bfloat16* row, int j, float v) {
    __nv_bfloat16 hi = __float2bfloat16(v);
    __nv_bfloat16 lo = __float2bfloat16(v - __bfloat162float(hi));
    row[j] = hi; row[256 + j] = lo;
}
__device__ __forceinline__ uint32_t smem_u32(const void* p) {
    uint32_t a;
    asm("{ .reg .u64 t; cvta.to.shared.u64 t, %1; cvt.u32.u64 %0, t; }" : "=r"(a) : "l"(p));
    return a;
}
__device__ __forceinline__ void cp_async16(uint32_t dst, const void* src, int sz) {
    asm volatile("cp.async.ca.shared.global [%0], [%1], 16, %2;"
                 :: "r"(dst), "l"(src), "r"(sz) : "memory");
}
__device__ __forceinline__ void ldmatrix_x4(uint32_t* r, uint32_t addr) {
    asm volatile("ldmatrix.sync.aligned.m8n8.x4.shared.b16 {%0,%1,%2,%3}, [%4];"
                 : "=r"(r[0]), "=r"(r[1]), "=r"(r[2]), "=r"(r[3]) : "r"(addr));
}
__device__ __forceinline__ void mma16816(float* c, const uint32_t* a, const uint32_t* b) {
    asm volatile(
        "mma.sync.aligned.m16n8k16.row.col.f32.bf16.bf16.f32 "
        "{%0,%1,%2,%3}, {%4,%5,%6,%7}, {%8,%9}, {%0,%1,%2,%3};"
        : "+f"(c[0]), "+f"(c[1]), "+f"(c[2]), "+f"(c[3])
        : "r"(a[0]), "r"(a[1]), "r"(a[2]), "r"(a[3]), "r"(b[0]), "r"(b[1]));
}

// --------------------------- pack kernels ----------------------------------
// Vectorized grid-stride split: 2 elements per thread per iteration.
__global__ void split_x(const float* __restrict__ x) {
    const int total_pairs = N_NODES * 128;          // pairs of elements
    for (int t = blockIdx.x * blockDim.x + threadIdx.x; t < total_pairs;
         t += gridDim.x * blockDim.x) {
        const int node = t >> 7;
        const int j = (t & 127) * 2;
        const float2 v = *(const float2*)(x + (size_t)node * 256 + j);
        __nv_bfloat16 h0 = __float2bfloat16(v.x);
        __nv_bfloat16 h1 = __float2bfloat16(v.y);
        __nv_bfloat162 hw = {h0, h1};
        __nv_bfloat162 lw = __floats2bfloat162_rn(v.x - __bfloat162float(h0),
                                                  v.y - __bfloat162float(h1));
        uint32_t* row = (uint32_t*)(g_x + (size_t)node * KP + j);
        row[0]   = *reinterpret_cast<uint32_t*>(&hw);
        row[128] = *reinterpret_cast<uint32_t*>(&lw);
    }
}

// Merged pack: Wcat(1024) | Wiou(768) | Wiouh(768) | Wfh(256) = 2816 blocks
__global__ void pack_all(const float* __restrict__ Wix, const float* __restrict__ bix,
                         const float* __restrict__ bih,
                         const float* __restrict__ Wfx, const float* __restrict__ bfx,
                         const float* __restrict__ bfh,
                         const float* __restrict__ Wiouh, const float* __restrict__ Wfh) {
    const int b = blockIdx.x;
    const int jj = threadIdx.x;
    if (b < 1024) {                     // Wcat rows p = 4j+g
        const int p = b;
        const int j = p >> 2, g = p & 3;
        float v = (g < 3) ? Wix[(g * 256 + j) * 256 + jj] : Wfx[j * 256 + jj];
        write2(&g_Wcat[(size_t)p * KP], jj, v);
        if (jj == 0)
            g_bcat[p] = (g < 3) ? (bix[g * 256 + j] + bih[g * 256 + j]) : (bfx[j] + bfh[j]);
    } else if (b < 1792) {              // Wiou row p = 3j+g (leaf)
        const int p = b - 1024;
        const int j = p / 3, g = p % 3;
        write2(&g_Wiou[(size_t)p * KP], jj, Wix[(g * 256 + j) * 256 + jj]);
        if (jj == 0) g_b3[p] = bix[g * 256 + j] + bih[g * 256 + j];
    } else if (b < 2560) {              // Wiouh row p = 3j+g
        const int p = b - 1792;
        const int j = p / 3, g = p % 3;
        write2(&g_Wiouh[(size_t)p * KP], jj, Wiouh[(g * 256 + j) * 256 + jj]);
    } else {                            // Wfh row r
        const int r = b - 2560;
        write2(&g_Wfh[(size_t)r * KP], jj, Wfh[r * 256 + jj]);
    }
}

// --------------------------- leaf GEMM (128x96, 2-stage, occ2) -------------
// Per k0: load Ah/Al/Bh/Bl tiles once; 3 compute passes (AhBh, AlBh, AhBl).
// Fused activation + level-7 hsum (in-place smem staging).
__global__ __launch_bounds__(256, 2)
void gemm_leaf(const __nv_bfloat16* __restrict__ A,      // g_x + LEAF_OFF*KP
               const __nv_bfloat16* __restrict__ B) {    // g_Wiou
    extern __shared__ __align__(16) char smd[];
    const int tid  = threadIdx.x;
    const int wid  = tid >> 5;
    const int lane = tid & 31;
    const int bm = blockIdx.y * 128;
    const int bn = blockIdx.x * 96;
    const int wm = (wid >> 1) * 32;
    const int wn = (wid & 1) * 48;
    const uint32_t sb = smem_u32(smd);

    float acc[2][6][4];
#pragma unroll
    for (int i = 0; i < 2; i++)
#pragma unroll
        for (int n = 0; n < 6; n++)
#pragma unroll
            for (int q = 0; q < 4; q++) acc[i][n][q] = 0.0f;

    // 1792 cp.async slots: Ah 512 | Al 512 | Bh 384 | Bl 384
#define LLOAD(c, st) do {                                                        \
        const int k0e = (c) * 32;                                                \
        uint32_t bs = sb + (st) * LSTG;                                          \
        _Pragma("unroll")                                                        \
        for (int s = 0; s < 7; s++) {                                            \
            int id = tid + s * 256;                                              \
            if (id < 512) {                                                      \
                int r = id >> 2, q = id & 3;                                     \
                cp_async16(bs + r * 80 + q * 16,                                 \
                           A + (size_t)(bm + r) * KP + k0e + q * 8, 16);         \
            } else if (id < 1024) {                                              \
                int o = id - 512; int r = o >> 2, q = o & 3;                     \
                cp_async16(bs + 10240 + r * 80 + q * 16,                         \
                           A + (size_t)(bm + r) * KP + 256 + k0e + q * 8, 16);   \
            } else if (id < 1408) {                                              \
                int o = id - 1024; int r = o >> 2, q = o & 3;                    \
                cp_async16(bs + 20480 + r * 80 + q * 16,                         \
                           B + (size_t)(bn + r) * KP + k0e + q * 8, 16);         \
            } else {                                                             \
                int o = id - 1408; int r = o >> 2, q = o & 3;                    \
                cp_async16(bs + 28160 + r * 80 + q * 16,                         \
                           B + (size_t)(bn + r) * KP + 256 + k0e + q * 8, 16);   \
            }                                                                    \
        }                                                                        \
        asm volatile("cp.async.commit_group;" ::: "memory");                     \
    } while (0)

    LLOAD(0, 0);
    const uint32_t lrow = lane & 15;
    const uint32_t lcol = (lane >> 4) * 16;

    for (int k0 = 0; k0 < NK0; k0++) {
        const int st = k0 & 1;
        if (k0 + 1 < NK0) {
            LLOAD(k0 + 1, st ^ 1);
            asm volatile("cp.async.wait_group 1;" ::: "memory");
        } else {
            asm volatile("cp.async.wait_group 0;" ::: "memory");
        }
        __syncthreads();

#pragma unroll 1
        for (int pass = 0; pass < 3; pass++) {
            const uint32_t aoff = (pass == 1) ? 10240u : 0u;
            const uint32_t boff = 20480u + ((pass == 2) ? 7680u : 0u);
            const uint32_t abase = sb + st * LSTG + aoff + (wm + lrow) * 80 + lcol;
            const uint32_t bbase = sb + st * LSTG + boff + (wn + lrow) * 80 + lcol;
#pragma unroll
            for (int ks = 0; ks < 2; ks++) {
                const uint32_t ko = ks * 32;
                uint32_t a[2][4];
                ldmatrix_x4(a[0], abase + ko);
                ldmatrix_x4(a[1], abase + 16 * 80 + ko);
                uint32_t bf[6][2];
#pragma unroll
                for (int j = 0; j < 3; j++) {
                    uint32_t r[4];
                    ldmatrix_x4(r, bbase + j * 16 * 80 + ko);
                    bf[2 * j][0] = r[0]; bf[2 * j][1] = r[2];
                    bf[2 * j + 1][0] = r[1]; bf[2 * j + 1][1] = r[3];
                }
#pragma unroll
                for (int i = 0; i < 2; i++)
#pragma unroll
                    for (int n = 0; n < 6; n++)
                        mma16816(acc[i][n], a[i], bf[n]);
            }
        }
        __syncthreads();
    }
#undef LLOAD

    // ---- stage tile to smem (aliases pipeline buffers) ----
    float* Cs = (float*)smd;
#pragma unroll
    for (int i = 0; i < 2; i++) {
        const int r = wm + i * 16 + (lane >> 2);
#pragma unroll
        for (int n = 0; n < 6; n++) {
            const int col = wn + n * 8 + (lane & 3) * 2;
            *(float2*)(Cs + r * LPITCH + col) = make_float2(acc[i][n][0], acc[i][n][1]);
            *(float2*)(Cs + (r + 8) * LPITCH + col) = make_float2(acc[i][n][2], acc[i][n][3]);
        }
    }
    __syncthreads();

    // ---- leaf activation: 128 rows x 32 features, 2 features per thread ----
    const int j0 = 32 * blockIdx.x;
#pragma unroll 2
    for (int it = 0; it < 8; it++) {
        const int idx = it * 256 + tid;
        const int r = idx >> 4;
        const int t = 2 * (idx & 15);
        float* cr = Cs + r * LPITCH + 3 * t;
        const float* bb = g_b3 + bn + 3 * t;
        float i0 = fsig (cr[0] + bb[0]);
        float o0 = fsig (cr[1] + bb[1]);
        float u0 = ftanh(cr[2] + bb[2]);
        float c0 = i0 * u0;
        float h0 = o0 * ftanh(c0);
        float i1 = fsig (cr[3] + bb[3]);
        float o1 = fsig (cr[4] + bb[4]);
        float u1 = ftanh(cr[5] + bb[5]);
        float c1 = i1 * u1;
        float h1 = o1 * ftanh(c1);

        const size_t node = (size_t)LEAF_OFF + bm + r;
        const int j = j0 + t;
        *(float2*)(g_c + node * 256 + j) = make_float2(c0, c1);

        __nv_bfloat16 hh0 = __float2bfloat16(h0);
        __nv_bfloat16 hh1 = __float2bfloat16(h1);
        float l0 = h0 - __bfloat162float(hh0);
        float l1 = h1 - __bfloat162float(hh1);
        uint32_t hiw; { __nv_bfloat162 p2 = {hh0, hh1}; hiw = *reinterpret_cast<uint32_t*>(&p2); }
        uint32_t low; { __nv_bfloat162 p2 = __floats2bfloat162_rn(l0, l1);
                        low = *reinterpret_cast<uint32_t*>(&p2); }
        uint32_t* hrow = (uint32_t*)(g_h + node * KP + j);
        hrow[0] = hiw;
        hrow[128] = low;

        // in-place fp32 h staging for the fused hsum pass
        cr[0] = h0;
        cr[3] = h1;
    }
    __syncthreads();

    // ---- fused level-7 hsum: 32 parents x 32 features per CTA ----
    const int kb = 32 * blockIdx.y;
#pragma unroll
    for (int v = 0; v < 4; v++) {
        const int lin = v * 256 + tid;
        const int pp = lin >> 5;
        const int tt = lin & 31;
        const float* hb = Cs + (4 * pp) * LPITCH + 3 * tt;
        float s = hb[0] + hb[LPITCH] + hb[2 * LPITCH] + hb[3 * LPITCH];
        write2(&g_hs[(size_t)(kb + pp) * KP], j0 + tt, s);
    }
}

// --------------------------- generic 128x128 mainloop ----------------------
__device__ __forceinline__ void mainloop128(
    const __nv_bfloat16* __restrict__ A, const __nv_bfloat16* __restrict__ B,
    int M, int bm, int bn, uint32_t sb, int tid, int wid, int lane,
    float (&acc)[2][8][4])
{
    const int wm = (wid >> 1) * 32;
    const int wn = (wid & 1) * 64;

    // 2048 cp.async slots: Ah 512 | Al 512 | Bh 512 | Bl 512
#define GLOAD(c, st) do {                                                        \
        const int k0e = (c) * 32;                                                \
        uint32_t bs = sb + (st) * GSTG;                                          \
        _Pragma("unroll")                                                        \
        for (int s = 0; s < 8; s++) {                                            \
            int id = tid + s * 256;                                              \
            int seg = id >> 9;                                                   \
            int o = id & 511;                                                    \
            int r = o >> 2, q = o & 3;                                           \
            if (seg == 0)                                                        \
                cp_async16(bs + r * 80 + q * 16,                                 \
                           A + (size_t)(bm + r) * KP + k0e + q * 8,              \
                           (bm + r < M) ? 16 : 0);                               \
            else if (seg == 1)                                                   \
                cp_async16(bs + 10240 + r * 80 + q * 16,                         \
                           A + (size_t)(bm + r) * KP + 256 + k0e + q * 8,        \
                           (bm + r < M) ? 16 : 0);                               \
            else if (seg == 2)                                                   \
                cp_async16(bs + 20480 + r * 80 + q * 16,                         \
                           B + (size_t)(bn + r) * KP + k0e + q * 8, 16);         \
            else                                                                 \
                cp_async16(bs + 30720 + r * 80 + q * 16,                         \
                           B + (size_t)(bn + r) * KP + 256 + k0e + q * 8, 16);   \
        }                                                                        \
        asm volatile("cp.async.commit_group;" ::: "memory");                     \
    } while (0)

    GLOAD(0, 0);
    const uint32_t lrow = lane & 15;
    const uint32_t lcol = (lane >> 4) * 16;

    for (int k0 = 0; k0 < NK0; k0++) {
        const int st = k0 & 1;
        if (k0 + 1 < NK0) {
            GLOAD(k0 + 1, st ^ 1);
            asm volatile("cp.async.wait_group 1;" ::: "memory");
        } else {
            asm volatile("cp.async.wait_group 0;" ::: "memory");
        }
        __syncthreads();

#pragma unroll 1
        for (int pass = 0; pass < 3; pass++) {
            const uint32_t aoff = (pass == 1) ? 10240u : 0u;
            const uint32_t boff = 20480u + ((pass == 2) ? 10240u : 0u);
            const uint32_t abase = sb + st * GSTG + aoff + (wm + lrow) * 80 + lcol;
            const uint32_t bbase = sb + st * GSTG + boff + (wn + lrow) * 80 + lcol;
#pragma unroll
            for (int ks = 0; ks < 2; ks++) {
                const uint32_t ko = ks * 32;
                uint32_t a[2][4];
                ldmatrix_x4(a[0], abase + ko);
                ldmatrix_x4(a[1], abase + 16 * 80 + ko);
                uint32_t bf[8][2];
#pragma unroll
                for (int j = 0; j < 4; j++) {
                    uint32_t r[4];
                    ldmatrix_x4(r, bbase + j * 16 * 80 + ko);
                    bf[2 * j][0] = r[0]; bf[2 * j][1] = r[2];
                    bf[2 * j + 1][0] = r[1]; bf[2 * j + 1][1] = r[3];
                }
#pragma unroll
                for (int i = 0; i < 2; i++)
#pragma unroll
                    for (int n = 0; n < 8; n++)
                        mma16816(acc[i][n], a[i], bf[n]);
            }
        }
        __syncthreads();
    }
#undef GLOAD
}

// --------------------------- dual-problem GEMM -----------------------------
__global__ __launch_bounds__(256, 2)
void gemm_dual(const __nv_bfloat16* A1, const __nv_bfloat16* B1, float* C1, int M1, int N1,
               const __nv_bfloat16* A2, const __nv_bfloat16* B2, float* C2, int M2, int N2) {
    extern __shared__ __align__(16) char smd[];
    const int tid  = threadIdx.x;
    const int wid  = tid >> 5;
    const int lane = tid & 31;
    const uint32_t sb = smem_u32(smd);

    const __nv_bfloat16 *A, *B;
    float* C;
    int M, Ntot, bm, bn;
    {
        const int nt1 = N1 >> 7, mt1 = (M1 + 127) >> 7;
        const int t1 = nt1 * mt1;
        int idx = blockIdx.x;
        if (idx < t1) {
            A = A1; B = B1; C = C1; M = M1; Ntot = N1;
            bm = (idx / nt1) * 128; bn = (idx % nt1) * 128;
        } else {
            idx -= t1;
            const int nt2 = N2 >> 7;
            A = A2; B = B2; C = C2; M = M2; Ntot = N2;
            bm = (idx / nt2) * 128; bn = (idx % nt2) * 128;
        }
    }

    float acc[2][8][4];
#pragma unroll
    for (int i = 0; i < 2; i++)
#pragma unroll
        for (int n = 0; n < 8; n++)
#pragma unroll
            for (int q = 0; q < 4; q++) acc[i][n][q] = 0.0f;

    mainloop128(A, B, M, bm, bn, sb, tid, wid, lane, acc);

    const int wm = (wid >> 1) * 32;
    const int wn = (wid & 1) * 64;
#pragma unroll
    for (int i = 0; i < 2; i++) {
        const int ra = bm + wm + i * 16 + (lane >> 2);
        const int rb = ra + 8;
#pragma unroll
        for (int n = 0; n < 8; n++) {
            const int col = bn + wn + n * 8 + (lane & 3) * 2;
            if (ra < M)
                *(float2*)(C + (size_t)ra * Ntot + col) =
                    make_float2(acc[i][n][0], acc[i][n][1]);
            if (rb < M)
                *(float2*)(C + (size_t)rb * Ntot + col) =
                    make_float2(acc[i][n][2], acc[i][n][3]);
        }
    }
}

// --------------------------- internal x-GEMM -------------------------------
__global__ __launch_bounds__(256, 2)
void gemm_big(const __nv_bfloat16* __restrict__ A, const __nv_bfloat16* __restrict__ B) {
    extern __shared__ __align__(16) char smd[];
    const int tid  = threadIdx.x;
    const int wid  = tid >> 5;
    const int lane = tid & 31;
    const int bm = blockIdx.y * 128;
    const int bn = blockIdx.x * 128;
    const int M = N_INT;
    const uint32_t sb = smem_u32(smd);

    float acc[2][8][4];
#pragma unroll
    for (int i = 0; i < 2; i++)
#pragma unroll
        for (int n = 0; n < 8; n++)
#pragma unroll
            for (int q = 0; q < 4; q++) acc[i][n][q] = 0.0f;

    mainloop128(A, B, M, bm, bn, sb, tid, wid, lane, acc);

    // stage C tile, then coalesced float4 XW stores (+bias)
    float* Cs = (float*)smd;
    const int wm = (wid >> 1) * 32;
    const int wn = (wid & 1) * 64;
#pragma unroll
    for (int i = 0; i < 2; i++) {
        const int ral = wm + i * 16 + (lane >> 2);
#pragma unroll
        for (int n = 0; n < 8; n++) {
            const int col = wn + n * 8 + (lane & 3) * 2;
            *(float2*)(Cs + ral * SPITCH + col) = make_float2(acc[i][n][0], acc[i][n][1]);
            *(float2*)(Cs + (ral + 8) * SPITCH + col) = make_float2(acc[i][n][2], acc[i][n][3]);
        }
    }
    __syncthreads();

#pragma unroll 4
    for (int it = 0; it < 16; it++) {
        const int idx = it * 256 + tid;
        const int r = idx >> 5;
        const int t = idx & 31;
        const int row = bm + r;
        if (row >= M) continue;
        float4 v = *(float4*)(Cs + r * SPITCH + 4 * t);
        const float4 b = *(const float4*)(g_bcat + bn + 4 * t);
        v.x += b.x; v.y += b.y; v.z += b.z; v.w += b.w;
        *(float4*)(g_XW + (size_t)row * 1024 + bn + 4 * t) = v;
    }
}

// --------------------------- fused combine + parent hsum -------------------
__global__ void combine_fused(int node_off, int child_off) {
    __shared__ float hsm[4][256];
    const int s = threadIdx.x >> 8;
    const int j = threadIdx.x & 255;
    const int k = 4 * blockIdx.x + s;
    const size_t node = (size_t)node_off + k;

    const float4 xw = *(const float4*)(g_XW + node * 1024 + 4 * j);
    const float* iouh = &g_iouh[(size_t)k * 768 + 3 * j];

    float iv = fsig (xw.x + iouh[0]);
    float ov = fsig (xw.y + iouh[1]);
    float uv = ftanh(xw.z + iouh[2]);
    const float fx = xw.w;

    float acc = 0.0f;
#pragma unroll
    for (int b = 0; b < 4; b++) {
        size_t ch = (size_t)child_off + 4 * (size_t)k + b;
        float f = fsig(fx + g_fh[(4 * (size_t)k + b) * 256 + j]);
        acc = fmaf(f, g_c[ch * 256 + j], acc);
    }
    float c = fmaf(iv, uv, acc);
    float h = ov * ftanh(c);
    g_c[node * 256 + j] = c;
    write2(&g_h[node * KP], j, h);

    hsm[s][j] = h;
    __syncthreads();
    if (s == 0) {
        float sum = hsm[0][j] + hsm[1][j] + hsm[2][j] + hsm[3][j];
        write2(&g_hs[(size_t)blockIdx.x * KP], j, sum);
    }
}

__global__ void combine_root() {
    const int j = threadIdx.x;
    const float4 xw = *(const float4*)(g_XW + 4 * j);
    const float* iouh = &g_iouh[3 * j];
    float iv = fsig (xw.x + iouh[0]);
    float ov = fsig (xw.y + iouh[1]);
    float uv = ftanh(xw.z + iouh[2]);
    const float fx = xw.w;
    float acc = 0.0f;
#pragma unroll
    for (int b = 0; b < 4; b++) {
        float f = fsig(fx + g_fh[b * 256 + j]);
        acc = fmaf(f, g_c[(1 + b) * 256 + j], acc);
    }
    float c = fmaf(iv, uv, acc);
    float h = ov * ftanh(c);
    g_c[j] = c;
    write2(&g_h[0], j, h);
}

__global__ void write_out(float* __restrict__ out) {
    int j = threadIdx.x;
    if (blockIdx.x == 0) out[j] = g_c[j];
    else out[256 + j] = __bfloat162float(g_h[j]) + __bfloat162float(g_h[256 + j]);
}

// --------------------------- launcher --------------------------------------
extern "C" void kernel_launch(void* const* d_in, const int* in_sizes, int n_in,
                              void* d_out, int out_size) {
    const float* x      = (const float*)d_in[0];
    const float* W_ioux = (const float*)d_in[1];
    const float* b_ioux = (const float*)d_in[2];
    const float* W_iouh = (const float*)d_in[3];
    const float* b_iouh = (const float*)d_in[4];
    const float* W_fx   = (const float*)d_in[5];
    const float* b_fx   = (const float*)d_in[6];
    const float* W_fh   = (const float*)d_in[7];
    const float* b_fh   = (const float*)d_in[8];

    cudaFuncSetAttribute(gemm_big,  cudaFuncAttributeMaxDynamicSharedMemorySize, BIG_SMEM);
    cudaFuncSetAttribute(gemm_dual, cudaFuncAttributeMaxDynamicSharedMemorySize, BIG_SMEM);
    cudaFuncSetAttribute(gemm_leaf, cudaFuncAttributeMaxDynamicSharedMemorySize, LEAF_SMEM);

    __nv_bfloat16 *xp, *hp, *hsp, *wcp, *wlp, *wip, *wfp;
    float *iouh, *fh;
    cudaGetSymbolAddress((void**)&xp,   g_x);
    cudaGetSymbolAddress((void**)&hp,   g_h);
    cudaGetSymbolAddress((void**)&hsp,  g_hs);
    cudaGetSymbolAddress((void**)&wcp,  g_Wcat);
    cudaGetSymbolAddress((void**)&wlp,  g_Wiou);
    cudaGetSymbolAddress((void**)&wip,  g_Wiouh);
    cudaGetSymbolAddress((void**)&wfp,  g_Wfh);
    cudaGetSymbolAddress((void**)&iouh, g_iouh);
    cudaGetSymbolAddress((void**)&fh,   g_fh);

    // 1-2: pack / split
    split_x<<<2048, 256>>>(x);
    pack_all<<<2816, 256>>>(W_ioux, b_ioux, b_iouh, W_fx, b_fx, b_fh, W_iouh, W_fh);

    // 3: dummy (keep leaf as 4th launch for ncu) — merged packs freed a slot,
    //    so launch order is: split, pack, leaf, big, ...
    // 4: leaf GEMM + fused activation + fused level-7 hsum (PROFILED LAUNCH)
    {
        dim3 grid(8, N_LEAVES / 128);
        gemm_leaf<<<grid, 256, LEAF_SMEM>>>(&xp[(size_t)LEAF_OFF * KP], wlp);
    }

    // 5: internal x-GEMM -> XW
    {
        dim3 grid(8, (N_INT + 127) / 128);
        gemm_big<<<grid, 256, BIG_SMEM>>>(xp, wcp);
    }

    // internal levels l = 7..0
    for (int l = 7; l >= 0; l--) {
        int n = 1 << (2 * l);
        int off = ((1 << (2 * l)) - 1) / 3;
        int choff = off + n;

        {   // fused dual GEMM: IOUH (n x 768) + FH (4n x 256)
            int mt1 = (n + 127) / 128;
            int mt2 = (4 * n + 127) / 128;
            int tiles = mt1 * 6 + mt2 * 2;
            gemm_dual<<<tiles, 256, BIG_SMEM>>>(hsp, wip, iouh, n, 768,
                                                &hp[(size_t)choff * KP], wfp,
                                                fh, 4 * n, 256);
        }
        if (l > 0) combine_fused<<<n / 4, 1024>>>(off, choff);
        else       combine_root<<<1, 256>>>();
    }

    write_out<<<2, 256>>>((float*)d_out);
}

// round 17
// speedup vs baseline: 1.9607x; 1.0170x over previous
#include <cuda_runtime.h>
#include <cuda_bf16.h>
#include <math.h>
#include <stdint.h>

// ---------------------------------------------------------------------------
// ChildSumTreeLSTM via HMMA (mma.sync bf16), fp32 accuracy via 3-term split:
//   acc = Ah*Bh + Al*Bh + Ah*Bl   (packed [hi|lo] K=512 rows, 3 passes/chunk)
// R16 structure (854.0us) + leaf GEMM and internal x-GEMM merged into ONE
// launch (gemm_main) so big's tiles backfill leaf's tail wave.
// ---------------------------------------------------------------------------

#define N_NODES   87381
#define N_INT     21845
#define LEAF_OFF  21845
#define N_LEAVES  65536
#define KP        512          // packed row: [hi(256) | lo(256)]
#define NK0       8            // 256/32 k0 chunks

#define LSTG      35840        // Ah 10240 | Al 10240 | Bh 7680 | Bl 7680
#define LPITCH    100
#define GSTG      40960        // Ah 10240 | Al 10240 | Bh 10240 | Bl 10240
#define SPITCH    132
#define BIG_SMEM  (2 * GSTG)   // 81920 >= SPITCH*128*4 (67584), >= 2*LSTG

#define LEAF_TILES 4096        // 8 x 512
#define BIG_TILES  1368        // 8 x 171

// --------------------------- device scratch --------------------------------
__device__ __align__(256) float         g_XW[(size_t)N_INT * 1024];     // 4j+g
__device__ __align__(256) float         g_c [(size_t)N_NODES * 256];
__device__ __align__(256) __nv_bfloat16 g_h [(size_t)N_NODES * KP];
__device__ __align__(256) __nv_bfloat16 g_x [(size_t)N_NODES * KP];
__device__ __align__(256) __nv_bfloat16 g_hs[(size_t)16384 * KP];
__device__ __align__(256) float         g_iouh[(size_t)16384 * 768];    // 3j+g
__device__ __align__(256) float         g_fh  [(size_t)65536 * 256];
__device__ __align__(256) __nv_bfloat16 g_Wcat [1024 * KP];             // 4j+g
__device__ __align__(256) __nv_bfloat16 g_Wiou [ 768 * KP];             // 3j+g
__device__ __align__(256) __nv_bfloat16 g_Wiouh[ 768 * KP];             // 3j+g
__device__ __align__(256) __nv_bfloat16 g_Wfh  [ 256 * KP];
__device__ float g_bcat[1024];                                          // 4j+g
__device__ float g_b3[768];                                             // 3j+g

// --------------------------- helpers ---------------------------------------
__device__ __forceinline__ float fsig(float v) {
    return __fdividef(1.0f, 1.0f + __expf(-v));
}
__device__ __forceinline__ float ftanh(float v) {
    float a = fabsf(v);
    float e = __expf(-2.0f * a);
    float t = __fdividef(1.0f - e, 1.0f + e);
    return copysignf(t, v);
}
// packed [hi|lo] write
__device__ __forceinline__ void write2(__nv_bfloat16* row, int j, float v) {
    __nv_bfloat16 hi = __float2bfloat16(v);
    __nv_bfloat16 lo = __float2bfloat16(v - __bfloat162float(hi));
    row[j] = hi; row[256 + j] = lo;
}
__device__ __forceinline__ uint32_t smem_u32(const void* p) {
    uint32_t a;
    asm("{ .reg .u64 t; cvta.to.shared.u64 t, %1; cvt.u32.u64 %0, t; }" : "=r"(a) : "l"(p));
    return a;
}
__device__ __forceinline__ void cp_async16(uint32_t dst, const void* src, int sz) {
    asm volatile("cp.async.ca.shared.global [%0], [%1], 16, %2;"
                 :: "r"(dst), "l"(src), "r"(sz) : "memory");
}
__device__ __forceinline__ void ldmatrix_x4(uint32_t* r, uint32_t addr) {
    asm volatile("ldmatrix.sync.aligned.m8n8.x4.shared.b16 {%0,%1,%2,%3}, [%4];"
                 : "=r"(r[0]), "=r"(r[1]), "=r"(r[2]), "=r"(r[3]) : "r"(addr));
}
__device__ __forceinline__ void mma16816(float* c, const uint32_t* a, const uint32_t* b) {
    asm volatile(
        "mma.sync.aligned.m16n8k16.row.col.f32.bf16.bf16.f32 "
        "{%0,%1,%2,%3}, {%4,%5,%6,%7}, {%8,%9}, {%0,%1,%2,%3};"
        : "+f"(c[0]), "+f"(c[1]), "+f"(c[2]), "+f"(c[3])
        : "r"(a[0]), "r"(a[1]), "r"(a[2]), "r"(a[3]), "r"(b[0]), "r"(b[1]));
}

// --------------------------- pack kernels ----------------------------------
// Vectorized grid-stride split: 2 elements per thread per iteration.
__global__ void split_x(const float* __restrict__ x) {
    const int total_pairs = N_NODES * 128;          // pairs of elements
    for (int t = blockIdx.x * blockDim.x + threadIdx.x; t < total_pairs;
         t += gridDim.x * blockDim.x) {
        const int node = t >> 7;
        const int j = (t & 127) * 2;
        const float2 v = *(const float2*)(x + (size_t)node * 256 + j);
        __nv_bfloat16 h0 = __float2bfloat16(v.x);
        __nv_bfloat16 h1 = __float2bfloat16(v.y);
        __nv_bfloat162 hw = {h0, h1};
        __nv_bfloat162 lw = __floats2bfloat162_rn(v.x - __bfloat162float(h0),
                                                  v.y - __bfloat162float(h1));
        uint32_t* row = (uint32_t*)(g_x + (size_t)node * KP + j);
        row[0]   = *reinterpret_cast<uint32_t*>(&hw);
        row[128] = *reinterpret_cast<uint32_t*>(&lw);
    }
}

// Merged pack: Wcat(1024) | Wiou(768) | Wiouh(768) | Wfh(256) = 2816 blocks
__global__ void pack_all(const float* __restrict__ Wix, const float* __restrict__ bix,
                         const float* __restrict__ bih,
                         const float* __restrict__ Wfx, const float* __restrict__ bfx,
                         const float* __restrict__ bfh,
                         const float* __restrict__ Wiouh, const float* __restrict__ Wfh) {
    const int b = blockIdx.x;
    const int jj = threadIdx.x;
    if (b < 1024) {                     // Wcat rows p = 4j+g
        const int p = b;
        const int j = p >> 2, g = p & 3;
        float v = (g < 3) ? Wix[(g * 256 + j) * 256 + jj] : Wfx[j * 256 + jj];
        write2(&g_Wcat[(size_t)p * KP], jj, v);
        if (jj == 0)
            g_bcat[p] = (g < 3) ? (bix[g * 256 + j] + bih[g * 256 + j]) : (bfx[j] + bfh[j]);
    } else if (b < 1792) {              // Wiou row p = 3j+g (leaf)
        const int p = b - 1024;
        const int j = p / 3, g = p % 3;
        write2(&g_Wiou[(size_t)p * KP], jj, Wix[(g * 256 + j) * 256 + jj]);
        if (jj == 0) g_b3[p] = bix[g * 256 + j] + bih[g * 256 + j];
    } else if (b < 2560) {              // Wiouh row p = 3j+g
        const int p = b - 1792;
        const int j = p / 3, g = p % 3;
        write2(&g_Wiouh[(size_t)p * KP], jj, Wiouh[(g * 256 + j) * 256 + jj]);
    } else {                            // Wfh row r
        const int r = b - 2560;
        write2(&g_Wfh[(size_t)r * KP], jj, Wfh[r * 256 + jj]);
    }
}

// --------------------------- leaf tile body (128x96) -----------------------
__device__ __forceinline__ void leaf_tile(const __nv_bfloat16* __restrict__ A,
                                          const __nv_bfloat16* __restrict__ B,
                                          int bnIdx, int bmIdx, char* smd) {
    const int tid  = threadIdx.x;
    const int wid  = tid >> 5;
    const int lane = tid & 31;
    const int bm = bmIdx * 128;
    const int bn = bnIdx * 96;
    const int wm = (wid >> 1) * 32;
    const int wn = (wid & 1) * 48;
    const uint32_t sb = smem_u32(smd);

    float acc[2][6][4];
#pragma unroll
    for (int i = 0; i < 2; i++)
#pragma unroll
        for (int n = 0; n < 6; n++)
#pragma unroll
            for (int q = 0; q < 4; q++) acc[i][n][q] = 0.0f;

#define LLOAD(c, st) do {                                                        \
        const int k0e = (c) * 32;                                                \
        uint32_t bs = sb + (st) * LSTG;                                          \
        _Pragma("unroll")                                                        \
        for (int s = 0; s < 7; s++) {                                            \
            int id = tid + s * 256;                                              \
            if (id < 512) {                                                      \
                int r = id >> 2, q = id & 3;                                     \
                cp_async16(bs + r * 80 + q * 16,                                 \
                           A + (size_t)(bm + r) * KP + k0e + q * 8, 16);         \
            } else if (id < 1024) {                                              \
                int o = id - 512; int r = o >> 2, q = o & 3;                     \
                cp_async16(bs + 10240 + r * 80 + q * 16,                         \
                           A + (size_t)(bm + r) * KP + 256 + k0e + q * 8, 16);   \
            } else if (id < 1408) {                                              \
                int o = id - 1024; int r = o >> 2, q = o & 3;                    \
                cp_async16(bs + 20480 + r * 80 + q * 16,                         \
                           B + (size_t)(bn + r) * KP + k0e + q * 8, 16);         \
            } else {                                                             \
                int o = id - 1408; int r = o >> 2, q = o & 3;                    \
                cp_async16(bs + 28160 + r * 80 + q * 16,                         \
                           B + (size_t)(bn + r) * KP + 256 + k0e + q * 8, 16);   \
            }                                                                    \
        }                                                                        \
        asm volatile("cp.async.commit_group;" ::: "memory");                     \
    } while (0)

    LLOAD(0, 0);
    const uint32_t lrow = lane & 15;
    const uint32_t lcol = (lane >> 4) * 16;

    for (int k0 = 0; k0 < NK0; k0++) {
        const int st = k0 & 1;
        if (k0 + 1 < NK0) {
            LLOAD(k0 + 1, st ^ 1);
            asm volatile("cp.async.wait_group 1;" ::: "memory");
        } else {
            asm volatile("cp.async.wait_group 0;" ::: "memory");
        }
        __syncthreads();

#pragma unroll 1
        for (int pass = 0; pass < 3; pass++) {
            const uint32_t aoff = (pass == 1) ? 10240u : 0u;
            const uint32_t boff = 20480u + ((pass == 2) ? 7680u : 0u);
            const uint32_t abase = sb + st * LSTG + aoff + (wm + lrow) * 80 + lcol;
            const uint32_t bbase = sb + st * LSTG + boff + (wn + lrow) * 80 + lcol;
#pragma unroll
            for (int ks = 0; ks < 2; ks++) {
                const uint32_t ko = ks * 32;
                uint32_t a[2][4];
                ldmatrix_x4(a[0], abase + ko);
                ldmatrix_x4(a[1], abase + 16 * 80 + ko);
                uint32_t bf[6][2];
#pragma unroll
                for (int j = 0; j < 3; j++) {
                    uint32_t r[4];
                    ldmatrix_x4(r, bbase + j * 16 * 80 + ko);
                    bf[2 * j][0] = r[0]; bf[2 * j][1] = r[2];
                    bf[2 * j + 1][0] = r[1]; bf[2 * j + 1][1] = r[3];
                }
#pragma unroll
                for (int i = 0; i < 2; i++)
#pragma unroll
                    for (int n = 0; n < 6; n++)
                        mma16816(acc[i][n], a[i], bf[n]);
            }
        }
        __syncthreads();
    }
#undef LLOAD

    // ---- stage tile to smem (aliases pipeline buffers) ----
    float* Cs = (float*)smd;
#pragma unroll
    for (int i = 0; i < 2; i++) {
        const int r = wm + i * 16 + (lane >> 2);
#pragma unroll
        for (int n = 0; n < 6; n++) {
            const int col = wn + n * 8 + (lane & 3) * 2;
            *(float2*)(Cs + r * LPITCH + col) = make_float2(acc[i][n][0], acc[i][n][1]);
            *(float2*)(Cs + (r + 8) * LPITCH + col) = make_float2(acc[i][n][2], acc[i][n][3]);
        }
    }
    __syncthreads();

    // ---- leaf activation: 128 rows x 32 features, 2 features per thread ----
    const int j0 = 32 * bnIdx;
#pragma unroll 2
    for (int it = 0; it < 8; it++) {
        const int idx = it * 256 + tid;
        const int r = idx >> 4;
        const int t = 2 * (idx & 15);
        float* cr = Cs + r * LPITCH + 3 * t;
        const float* bb = g_b3 + bn + 3 * t;
        float i0 = fsig (cr[0] + bb[0]);
        float o0 = fsig (cr[1] + bb[1]);
        float u0 = ftanh(cr[2] + bb[2]);
        float c0 = i0 * u0;
        float h0 = o0 * ftanh(c0);
        float i1 = fsig (cr[3] + bb[3]);
        float o1 = fsig (cr[4] + bb[4]);
        float u1 = ftanh(cr[5] + bb[5]);
        float c1 = i1 * u1;
        float h1 = o1 * ftanh(c1);

        const size_t node = (size_t)LEAF_OFF + bm + r;
        const int j = j0 + t;
        *(float2*)(g_c + node * 256 + j) = make_float2(c0, c1);

        __nv_bfloat16 hh0 = __float2bfloat16(h0);
        __nv_bfloat16 hh1 = __float2bfloat16(h1);
        float l0 = h0 - __bfloat162float(hh0);
        float l1 = h1 - __bfloat162float(hh1);
        uint32_t hiw; { __nv_bfloat162 p2 = {hh0, hh1}; hiw = *reinterpret_cast<uint32_t*>(&p2); }
        uint32_t low; { __nv_bfloat162 p2 = __floats2bfloat162_rn(l0, l1);
                        low = *reinterpret_cast<uint32_t*>(&p2); }
        uint32_t* hrow = (uint32_t*)(g_h + node * KP + j);
        hrow[0] = hiw;
        hrow[128] = low;

        // in-place fp32 h staging for the fused hsum pass
        cr[0] = h0;
        cr[3] = h1;
    }
    __syncthreads();

    // ---- fused level-7 hsum: 32 parents x 32 features per CTA ----
    const int kb = 32 * bmIdx;
#pragma unroll
    for (int v = 0; v < 4; v++) {
        const int lin = v * 256 + tid;
        const int pp = lin >> 5;
        const int tt = lin & 31;
        const float* hb = Cs + (4 * pp) * LPITCH + 3 * tt;
        float s = hb[0] + hb[LPITCH] + hb[2 * LPITCH] + hb[3 * LPITCH];
        write2(&g_hs[(size_t)(kb + pp) * KP], j0 + tt, s);
    }
}

// --------------------------- generic 128x128 mainloop ----------------------
__device__ __forceinline__ void mainloop128(
    const __nv_bfloat16* __restrict__ A, const __nv_bfloat16* __restrict__ B,
    int M, int bm, int bn, uint32_t sb, int tid, int wid, int lane,
    float (&acc)[2][8][4])
{
    const int wm = (wid >> 1) * 32;
    const int wn = (wid & 1) * 64;

#define GLOAD(c, st) do {                                                        \
        const int k0e = (c) * 32;                                                \
        uint32_t bs = sb + (st) * GSTG;                                          \
        _Pragma("unroll")                                                        \
        for (int s = 0; s < 8; s++) {                                            \
            int id = tid + s * 256;                                              \
            int seg = id >> 9;                                                   \
            int o = id & 511;                                                    \
            int r = o >> 2, q = o & 3;                                           \
            if (seg == 0)                                                        \
                cp_async16(bs + r * 80 + q * 16,                                 \
                           A + (size_t)(bm + r) * KP + k0e + q * 8,              \
                           (bm + r < M) ? 16 : 0);                               \
            else if (seg == 1)                                                   \
                cp_async16(bs + 10240 + r * 80 + q * 16,                         \
                           A + (size_t)(bm + r) * KP + 256 + k0e + q * 8,        \
                           (bm + r < M) ? 16 : 0);                               \
            else if (seg == 2)                                                   \
                cp_async16(bs + 20480 + r * 80 + q * 16,                         \
                           B + (size_t)(bn + r) * KP + k0e + q * 8, 16);         \
            else                                                                 \
                cp_async16(bs + 30720 + r * 80 + q * 16,                         \
                           B + (size_t)(bn + r) * KP + 256 + k0e + q * 8, 16);   \
        }                                                                        \
        asm volatile("cp.async.commit_group;" ::: "memory");                     \
    } while (0)

    GLOAD(0, 0);
    const uint32_t lrow = lane & 15;
    const uint32_t lcol = (lane >> 4) * 16;

    for (int k0 = 0; k0 < NK0; k0++) {
        const int st = k0 & 1;
        if (k0 + 1 < NK0) {
            GLOAD(k0 + 1, st ^ 1);
            asm volatile("cp.async.wait_group 1;" ::: "memory");
        } else {
            asm volatile("cp.async.wait_group 0;" ::: "memory");
        }
        __syncthreads();

#pragma unroll 1
        for (int pass = 0; pass < 3; pass++) {
            const uint32_t aoff = (pass == 1) ? 10240u : 0u;
            const uint32_t boff = 20480u + ((pass == 2) ? 10240u : 0u);
            const uint32_t abase = sb + st * GSTG + aoff + (wm + lrow) * 80 + lcol;
            const uint32_t bbase = sb + st * GSTG + boff + (wn + lrow) * 80 + lcol;
#pragma unroll
            for (int ks = 0; ks < 2; ks++) {
                const uint32_t ko = ks * 32;
                uint32_t a[2][4];
                ldmatrix_x4(a[0], abase + ko);
                ldmatrix_x4(a[1], abase + 16 * 80 + ko);
                uint32_t bf[8][2];
#pragma unroll
                for (int j = 0; j < 4; j++) {
                    uint32_t r[4];
                    ldmatrix_x4(r, bbase + j * 16 * 80 + ko);
                    bf[2 * j][0] = r[0]; bf[2 * j][1] = r[2];
                    bf[2 * j + 1][0] = r[1]; bf[2 * j + 1][1] = r[3];
                }
#pragma unroll
                for (int i = 0; i < 2; i++)
#pragma unroll
                    for (int n = 0; n < 8; n++)
                        mma16816(acc[i][n], a[i], bf[n]);
            }
        }
        __syncthreads();
    }
#undef GLOAD
}

// --------------------------- internal-x tile body (128x128) ----------------
__device__ __forceinline__ void big_tile(const __nv_bfloat16* __restrict__ A,
                                         const __nv_bfloat16* __restrict__ B,
                                         int bm, int bn, char* smd) {
    const int tid  = threadIdx.x;
    const int wid  = tid >> 5;
    const int lane = tid & 31;
    const int M = N_INT;
    const uint32_t sb = smem_u32(smd);

    float acc[2][8][4];
#pragma unroll
    for (int i = 0; i < 2; i++)
#pragma unroll
        for (int n = 0; n < 8; n++)
#pragma unroll
            for (int q = 0; q < 4; q++) acc[i][n][q] = 0.0f;

    mainloop128(A, B, M, bm, bn, sb, tid, wid, lane, acc);

    // stage C tile, then coalesced float4 XW stores (+bias)
    float* Cs = (float*)smd;
    const int wm = (wid >> 1) * 32;
    const int wn = (wid & 1) * 64;
#pragma unroll
    for (int i = 0; i < 2; i++) {
        const int ral = wm + i * 16 + (lane >> 2);
#pragma unroll
        for (int n = 0; n < 8; n++) {
            const int col = wn + n * 8 + (lane & 3) * 2;
            *(float2*)(Cs + ral * SPITCH + col) = make_float2(acc[i][n][0], acc[i][n][1]);
            *(float2*)(Cs + (ral + 8) * SPITCH + col) = make_float2(acc[i][n][2], acc[i][n][3]);
        }
    }
    __syncthreads();

#pragma unroll 4
    for (int it = 0; it < 16; it++) {
        const int idx = it * 256 + tid;
        const int r = idx >> 5;
        const int t = idx & 31;
        const int row = bm + r;
        if (row >= M) continue;
        float4 v = *(float4*)(Cs + r * SPITCH + 4 * t);
        const float4 b = *(const float4*)(g_bcat + bn + 4 * t);
        v.x += b.x; v.y += b.y; v.z += b.z; v.w += b.w;
        *(float4*)(g_XW + (size_t)row * 1024 + bn + 4 * t) = v;
    }
}

// --------------------------- merged main GEMM ------------------------------
__global__ __launch_bounds__(256, 2)
void gemm_main(const __nv_bfloat16* Al, const __nv_bfloat16* Bl,
               const __nv_bfloat16* Ab, const __nv_bfloat16* Bb) {
    extern __shared__ __align__(16) char smd[];
    int idx = blockIdx.x;
    if (idx < LEAF_TILES) {
        leaf_tile(Al, Bl, idx & 7, idx >> 3, smd);
    } else {
        idx -= LEAF_TILES;
        big_tile(Ab, Bb, (idx >> 3) * 128, (idx & 7) * 128, smd);
    }
}

// --------------------------- dual-problem GEMM -----------------------------
__global__ __launch_bounds__(256, 2)
void gemm_dual(const __nv_bfloat16* A1, const __nv_bfloat16* B1, float* C1, int M1, int N1,
               const __nv_bfloat16* A2, const __nv_bfloat16* B2, float* C2, int M2, int N2) {
    extern __shared__ __align__(16) char smd[];
    const int tid  = threadIdx.x;
    const int wid  = tid >> 5;
    const int lane = tid & 31;
    const uint32_t sb = smem_u32(smd);

    const __nv_bfloat16 *A, *B;
    float* C;
    int M, Ntot, bm, bn;
    {
        const int nt1 = N1 >> 7, mt1 = (M1 + 127) >> 7;
        const int t1 = nt1 * mt1;
        int idx = blockIdx.x;
        if (idx < t1) {
            A = A1; B = B1; C = C1; M = M1; Ntot = N1;
            bm = (idx / nt1) * 128; bn = (idx % nt1) * 128;
        } else {
            idx -= t1;
            const int nt2 = N2 >> 7;
            A = A2; B = B2; C = C2; M = M2; Ntot = N2;
            bm = (idx / nt2) * 128; bn = (idx % nt2) * 128;
        }
    }

    float acc[2][8][4];
#pragma unroll
    for (int i = 0; i < 2; i++)
#pragma unroll
        for (int n = 0; n < 8; n++)
#pragma unroll
            for (int q = 0; q < 4; q++) acc[i][n][q] = 0.0f;

    mainloop128(A, B, M, bm, bn, sb, tid, wid, lane, acc);

    const int wm = (wid >> 1) * 32;
    const int wn = (wid & 1) * 64;
#pragma unroll
    for (int i = 0; i < 2; i++) {
        const int ra = bm + wm + i * 16 + (lane >> 2);
        const int rb = ra + 8;
#pragma unroll
        for (int n = 0; n < 8; n++) {
            const int col = bn + wn + n * 8 + (lane & 3) * 2;
            if (ra < M)
                *(float2*)(C + (size_t)ra * Ntot + col) =
                    make_float2(acc[i][n][0], acc[i][n][1]);
            if (rb < M)
                *(float2*)(C + (size_t)rb * Ntot + col) =
                    make_float2(acc[i][n][2], acc[i][n][3]);
        }
    }
}

// --------------------------- fused combine + parent hsum -------------------
__global__ void combine_fused(int node_off, int child_off) {
    __shared__ float hsm[4][256];
    const int s = threadIdx.x >> 8;
    const int j = threadIdx.x & 255;
    const int k = 4 * blockIdx.x + s;
    const size_t node = (size_t)node_off + k;

    const float4 xw = *(const float4*)(g_XW + node * 1024 + 4 * j);
    const float* iouh = &g_iouh[(size_t)k * 768 + 3 * j];

    float iv = fsig (xw.x + iouh[0]);
    float ov = fsig (xw.y + iouh[1]);
    float uv = ftanh(xw.z + iouh[2]);
    const float fx = xw.w;

    float acc = 0.0f;
#pragma unroll
    for (int b = 0; b < 4; b++) {
        size_t ch = (size_t)child_off + 4 * (size_t)k + b;
        float f = fsig(fx + g_fh[(4 * (size_t)k + b) * 256 + j]);
        acc = fmaf(f, g_c[ch * 256 + j], acc);
    }
    float c = fmaf(iv, uv, acc);
    float h = ov * ftanh(c);
    g_c[node * 256 + j] = c;
    write2(&g_h[node * KP], j, h);

    hsm[s][j] = h;
    __syncthreads();
    if (s == 0) {
        float sum = hsm[0][j] + hsm[1][j] + hsm[2][j] + hsm[3][j];
        write2(&g_hs[(size_t)blockIdx.x * KP], j, sum);
    }
}

__global__ void combine_root() {
    const int j = threadIdx.x;
    const float4 xw = *(const float4*)(g_XW + 4 * j);
    const float* iouh = &g_iouh[3 * j];
    float iv = fsig (xw.x + iouh[0]);
    float ov = fsig (xw.y + iouh[1]);
    float uv = ftanh(xw.z + iouh[2]);
    const float fx = xw.w;
    float acc = 0.0f;
#pragma unroll
    for (int b = 0; b < 4; b++) {
        float f = fsig(fx + g_fh[b * 256 + j]);
        acc = fmaf(f, g_c[(1 + b) * 256 + j], acc);
    }
    float c = fmaf(iv, uv, acc);
    float h = ov * ftanh(c);
    g_c[j] = c;
    write2(&g_h[0], j, h);
}

__global__ void write_out(float* __restrict__ out) {
    int j = threadIdx.x;
    if (blockIdx.x == 0) out[j] = g_c[j];
    else out[256 + j] = __bfloat162float(g_h[j]) + __bfloat162float(g_h[256 + j]);
}

// --------------------------- launcher --------------------------------------
extern "C" void kernel_launch(void* const* d_in, const int* in_sizes, int n_in,
                              void* d_out, int out_size) {
    const float* x      = (const float*)d_in[0];
    const float* W_ioux = (const float*)d_in[1];
    const float* b_ioux = (const float*)d_in[2];
    const float* W_iouh = (const float*)d_in[3];
    const float* b_iouh = (const float*)d_in[4];
    const float* W_fx   = (const float*)d_in[5];
    const float* b_fx   = (const float*)d_in[6];
    const float* W_fh   = (const float*)d_in[7];
    const float* b_fh   = (const float*)d_in[8];

    cudaFuncSetAttribute(gemm_main, cudaFuncAttributeMaxDynamicSharedMemorySize, BIG_SMEM);
    cudaFuncSetAttribute(gemm_dual, cudaFuncAttributeMaxDynamicSharedMemorySize, BIG_SMEM);

    __nv_bfloat16 *xp, *hp, *hsp, *wcp, *wlp, *wip, *wfp;
    float *iouh, *fh;
    cudaGetSymbolAddress((void**)&xp,   g_x);
    cudaGetSymbolAddress((void**)&hp,   g_h);
    cudaGetSymbolAddress((void**)&hsp,  g_hs);
    cudaGetSymbolAddress((void**)&wcp,  g_Wcat);
    cudaGetSymbolAddress((void**)&wlp,  g_Wiou);
    cudaGetSymbolAddress((void**)&wip,  g_Wiouh);
    cudaGetSymbolAddress((void**)&wfp,  g_Wfh);
    cudaGetSymbolAddress((void**)&iouh, g_iouh);
    cudaGetSymbolAddress((void**)&fh,   g_fh);

    // 1-2: pack / split
    split_x<<<2048, 256>>>(x);
    pack_all<<<2816, 256>>>(W_ioux, b_ioux, b_iouh, W_fx, b_fx, b_fh, W_iouh, W_fh);

    // 3: merged leaf + internal-x GEMM (single launch; PROFILED LAUNCH)
    gemm_main<<<LEAF_TILES + BIG_TILES, 256, BIG_SMEM>>>(
        &xp[(size_t)LEAF_OFF * KP], wlp, xp, wcp);

    // internal levels l = 7..0
    for (int l = 7; l >= 0; l--) {
        int n = 1 << (2 * l);
        int off = ((1 << (2 * l)) - 1) / 3;
        int choff = off + n;

        {   // fused dual GEMM: IOUH (n x 768) + FH (4n x 256)
            int mt1 = (n + 127) / 128;
            int mt2 = (4 * n + 127) / 128;
            int tiles = mt1 * 6 + mt2 * 2;
            gemm_dual<<<tiles, 256, BIG_SMEM>>>(hsp, wip, iouh, n, 768,
                                                &hp[(size_t)choff * KP], wfp,
                                                fh, 4 * n, 256);
        }
        if (l > 0) combine_fused<<<n / 4, 1024>>>(off, choff);
        else       combine_root<<<1, 256>>>();
    }

    write_out<<<2, 256>>>((float*)d_out);
}